// round 2
// baseline (speedup 1.0000x reference)
#include <cuda_runtime.h>
#include <math.h>

#define BT   64      // threads per block = points per block
#define NCH  101     // 100 SH channels + 1 time index
#define LMAX 10

__global__ __launch_bounds__(BT) void sh_kernel(const float* __restrict__ lonlat,
                                                float* __restrict__ out,
                                                int N) {
    __shared__ __align__(16) float stage[BT * NCH];
    __shared__ float sK[55];

    const int tid = threadIdx.x;

    // ---- per-block: compute normalization constants K(l,|m|) (55 entries) ----
    if (tid < 55) {
        int l = 0, tri = 0;
        while (tri + l + 1 <= tid) { tri += l + 1; l++; }
        int am = tid - tri;
        float ratio = 1.0f;                 // (l-am)! / (l+am)!
        for (int k = l - am + 1; k <= l + am; k++) ratio /= (float)k;
        float K = sqrtf((float)(2 * l + 1) * 0.07957747154594767f * ratio); // 1/(4*pi)
        if (am > 0) K *= 1.41421356237309515f;   // sqrt(2) folded in for |m|>0
        sK[tid] = K;
    }
    __syncthreads();

    const long long i = (long long)blockIdx.x * BT + tid;
    if (i < N) {
        const float lon = lonlat[i * 3 + 0];
        const float lat = lonlat[i * 3 + 1];
        const float t   = lonlat[i * 3 + 2];

        const float D2R = 0.017453292519943295f;
        const float phi = (lon + 180.0f) * D2R;
        const float th  = (lat +  90.0f) * D2R;

        float s, x;                 // s = sin(theta), x = cos(theta)
        sincosf(th, &s, &x);
        float s1, c1;               // sin(phi), cos(phi)
        sincosf(phi, &s1, &c1);

        // cos(m*phi), sin(m*phi) by angle-addition recurrence
        float cmv[LMAX], smv[LMAX];
        cmv[0] = 1.0f; smv[0] = 0.0f;
        #pragma unroll
        for (int m = 1; m < LMAX; m++) {
            cmv[m] = cmv[m - 1] * c1 - smv[m - 1] * s1;
            smv[m] = smv[m - 1] * c1 + cmv[m - 1] * s1;
        }

        float* st = &stage[tid * NCH];

        // Associated Legendre chains per m; write Y directly to staging smem.
        float pmm = 1.0f;
        #pragma unroll
        for (int m = 0; m < LMAX; m++) {
            if (m > 0) pmm *= (float)(-(2 * m - 1)) * s;
            float plm2 = pmm;                          // P[m][m]
            {
                const int l = m;
                const float Kc = sK[l * (l + 1) / 2 + m];
                if (m == 0) {
                    st[l * l + l] = Kc * plm2;
                } else {
                    st[l * l + l + m] = Kc * cmv[m] * plm2;
                    st[l * l + l - m] = Kc * smv[m] * plm2;
                }
            }
            if (m + 1 < LMAX) {
                float plm1 = x * (float)(2 * m + 1) * pmm;   // P[m+1][m]
                {
                    const int l = m + 1;
                    const float Kc = sK[l * (l + 1) / 2 + m];
                    if (m == 0) {
                        st[l * l + l] = Kc * plm1;
                    } else {
                        st[l * l + l + m] = Kc * cmv[m] * plm1;
                        st[l * l + l - m] = Kc * smv[m] * plm1;
                    }
                }
                #pragma unroll
                for (int l = m + 2; l < LMAX; l++) {
                    const float pl = ((float)(2 * l - 1) * x * plm1
                                      - (float)(l + m - 1) * plm2) * (1.0f / (float)(l - m));
                    plm2 = plm1;
                    plm1 = pl;
                    const float Kc = sK[l * (l + 1) / 2 + m];
                    if (m == 0) {
                        st[l * l + l] = Kc * pl;
                    } else {
                        st[l * l + l + m] = Kc * cmv[m] * pl;
                        st[l * l + l - m] = Kc * smv[m] * pl;
                    }
                }
            }
        }
        st[100] = t;
    }
    __syncthreads();

    // ---- coalesced copy-out of the block tile ----
    const long long blockBase = (long long)blockIdx.x * BT;
    long long rem = (long long)N - blockBase;
    const int nvalid = (rem >= BT) ? BT : (rem > 0 ? (int)rem : 0);

    if (nvalid == BT) {
        const float4* s4 = (const float4*)stage;
        float4* o4 = (float4*)(out + blockBase * NCH);
        #pragma unroll 4
        for (int j = tid; j < (BT * NCH) / 4; j += BT) {
            o4[j] = s4[j];
        }
    } else if (nvalid > 0) {
        const int tot = nvalid * NCH;
        float* o = out + blockBase * NCH;
        for (int j = tid; j < tot; j += BT) {
            o[j] = stage[j];
        }
    }
}

extern "C" void kernel_launch(void* const* d_in, const int* in_sizes, int n_in,
                              void* d_out, int out_size) {
    const float* lonlat = (const float*)d_in[0];
    const int N = in_sizes[0] / 3;
    float* out = (float*)d_out;
    const int nb = (N + BT - 1) / BT;
    sh_kernel<<<nb, BT>>>(lonlat, out, N);
}

// round 3
// speedup vs baseline: 1.1773x; 1.1773x over previous
#include <cuda_runtime.h>
#include <math.h>

#define BT   128     // threads per block (2 warps per 32-point group)
#define PT   64      // points per block
#define NCH  101     // 100 SH channels + 1 time index
#define LMAX 10

// Per-half SH compute: handles m = M0, M0+2, ..., fully unrolled so every
// (l,m) integer constant folds to a float immediate.
template <int M0>
__device__ __forceinline__ void sh_half(float x, float s, float c1, float s1,
                                        float* __restrict__ st,
                                        const float* __restrict__ sK) {
    const float c2 = c1 * c1 - s1 * s1;
    const float s2 = 2.0f * c1 * s1;
    float cm, sm, pmm;
    if (M0 == 0) { cm = 1.0f; sm = 0.0f; pmm = 1.0f; }
    else         { cm = c1;   sm = s1;   pmm = -s;   }

    #pragma unroll
    for (int mi = 0; mi < 5; mi++) {
        const int m = M0 + 2 * mi;

        float plm2 = pmm;                                  // P[m][m]
        {
            const int l = m;
            const float Kc = sK[l * (l + 1) / 2 + m];
            if (m == 0) st[0] = Kc * plm2;
            else {
                st[l * l + l + m] = Kc * cm * plm2;
                st[l * l + l - m] = Kc * sm * plm2;
            }
        }
        if (m + 1 < LMAX) {
            float plm1 = x * (float)(2 * m + 1) * pmm;     // P[m+1][m]
            {
                const int l = m + 1;
                const float Kc = sK[l * (l + 1) / 2 + m];
                if (m == 0) st[l * l + l] = Kc * plm1;
                else {
                    st[l * l + l + m] = Kc * cm * plm1;
                    st[l * l + l - m] = Kc * sm * plm1;
                }
            }
            #pragma unroll
            for (int l = m + 2; l < LMAX; l++) {
                const float pl = ((float)(2 * l - 1) * x * plm1
                                  - (float)(l + m - 1) * plm2) * (1.0f / (float)(l - m));
                plm2 = plm1;
                plm1 = pl;
                const float Kc = sK[l * (l + 1) / 2 + m];
                if (m == 0) st[l * l + l] = Kc * pl;
                else {
                    st[l * l + l + m] = Kc * cm * pl;
                    st[l * l + l - m] = Kc * sm * pl;
                }
            }
        }

        if (mi < 4) {
            // advance m -> m+2
            pmm *= (float)((2 * m + 1) * (2 * m + 3)) * s * s;
            const float cn = cm * c2 - sm * s2;
            const float sn = sm * c2 + cm * s2;
            cm = cn; sm = sn;
        }
    }
}

__global__ __launch_bounds__(BT) void sh_kernel(const float* __restrict__ lonlat,
                                                float* __restrict__ out,
                                                int N) {
    __shared__ __align__(16) float stage[PT * NCH];
    __shared__ float sK[55];

    const int tid  = threadIdx.x;
    const int wid  = tid >> 5;
    const int lane = tid & 31;

    // ---- per-block: normalization constants K(l,|m|), 55 entries ----
    if (tid < 55) {
        int l = 0, tri = 0;
        while (tri + l + 1 <= tid) { tri += l + 1; l++; }
        int am = tid - tri;
        float ratio = 1.0f;                      // (l-am)! / (l+am)!
        for (int k = l - am + 1; k <= l + am; k++) ratio /= (float)k;
        float K = sqrtf((float)(2 * l + 1) * 0.07957747154594767f * ratio);
        if (am > 0) K *= 1.41421356237309515f;   // fold sqrt(2)
        sK[tid] = K;
    }
    __syncthreads();

    // warp pair layout: warps {0,1} -> points 0..31, warps {2,3} -> points 32..63
    const int p = lane + (wid >> 1) * 32;        // point within block
    const int half = wid & 1;                    // 0: even m, 1: odd m
    const long long i = (long long)blockIdx.x * PT + p;

    if (i < N) {
        const float lon = lonlat[i * 3 + 0];
        const float lat = lonlat[i * 3 + 1];

        const float D2R = 0.017453292519943295f;
        const float phi = (lon + 180.0f) * D2R;
        const float th  = (lat +  90.0f) * D2R;

        float s, x;                  // sin(theta), cos(theta)
        sincosf(th, &s, &x);
        float s1, c1;                // sin(phi), cos(phi)
        sincosf(phi, &s1, &c1);

        float* st = &stage[p * NCH];
        if (half == 0) {
            sh_half<0>(x, s, c1, s1, st, sK);
            st[100] = lonlat[i * 3 + 2];         // time index
        } else {
            sh_half<1>(x, s, c1, s1, st, sK);
        }
    }
    __syncthreads();

    // ---- coalesced streaming copy-out of the block tile ----
    const long long blockBase = (long long)blockIdx.x * PT;
    long long rem = (long long)N - blockBase;
    const int nvalid = (rem >= PT) ? PT : (rem > 0 ? (int)rem : 0);

    if (nvalid == PT) {
        const float4* s4 = (const float4*)stage;
        float4* o4 = (float4*)(out + blockBase * NCH);
        #pragma unroll 4
        for (int j = tid; j < (PT * NCH) / 4; j += BT) {
            __stcs(&o4[j], s4[j]);
        }
    } else if (nvalid > 0) {
        const int tot = nvalid * NCH;
        float* o = out + blockBase * NCH;
        for (int j = tid; j < tot; j += BT) {
            __stcs(&o[j], stage[j]);
        }
    }
}

extern "C" void kernel_launch(void* const* d_in, const int* in_sizes, int n_in,
                              void* d_out, int out_size) {
    const float* lonlat = (const float*)d_in[0];
    const int N = in_sizes[0] / 3;
    float* out = (float*)d_out;
    const int nb = (N + PT - 1) / PT;
    sh_kernel<<<nb, BT>>>(lonlat, out, N);
}